// round 2
// baseline (speedup 1.0000x reference)
#include <cuda_runtime.h>
#include <math.h>

// ---------------------------------------------------------------------------
// GaussianSceneModel: 1M gaussians -> camera (rgb, depth, alpha) + lidar
// (depth, alpha) via bilinear scatter splatting.
// All projection arithmetic uses explicit IEEE intrinsics (__fmul_rn etc.)
// to bit-match the fp32 reference (no FMA contraction, true division).
// ---------------------------------------------------------------------------

#define W_IMG   1600
#define H_IMG   900
#define WL_IMG  1024
#define HL_IMG  128
#define CAM_PIX (W_IMG * H_IMG)          // 1,440,000
#define LID_PIX (WL_IMG * HL_IMG)        // 131,072
#define OFF_RGB   0
#define OFF_DEPTH (3 * CAM_PIX)
#define OFF_ALPHA (4 * CAM_PIX)
#define OFF_LD    (5 * CAM_PIX)
#define OFF_LA    (5 * CAM_PIX + LID_PIX)
#define OUT_ELEMS (5 * CAM_PIX + 2 * LID_PIX)

// math.radians(-25) and math.radians(3) as float64, cast to fp32 like JAX does
#define FMIN_F ((float)(-0.4363323129985824))
#define FMAX_F ((float)(0.05235987755982988))
// (fmax - fmin) computed in float64 then cast (python scalar arithmetic)
#define FRANGE_F ((float)(0.05235987755982988 + 0.4363323129985824))
#define TWO_PI_F ((float)(6.283185307179586))
#define NEAR_PLANE 1.0f
#define FAR_PLANE  100.0f
#define EPS 1e-8f

struct Params {
    float w2c[12];
    float w2l[12];
    float fx, fy, cx, cy;
};
__device__ Params g_P;

__device__ void inv4x4(const float* m, float* invOut) {
    float inv[16];
    inv[0] = m[5]*m[10]*m[15] - m[5]*m[11]*m[14] - m[9]*m[6]*m[15] +
             m[9]*m[7]*m[14] + m[13]*m[6]*m[11] - m[13]*m[7]*m[10];
    inv[4] = -m[4]*m[10]*m[15] + m[4]*m[11]*m[14] + m[8]*m[6]*m[15] -
             m[8]*m[7]*m[14] - m[12]*m[6]*m[11] + m[12]*m[7]*m[10];
    inv[8] = m[4]*m[9]*m[15] - m[4]*m[11]*m[13] - m[8]*m[5]*m[15] +
             m[8]*m[7]*m[13] + m[12]*m[5]*m[11] - m[12]*m[7]*m[9];
    inv[12] = -m[4]*m[9]*m[14] + m[4]*m[10]*m[13] + m[8]*m[5]*m[14] -
              m[8]*m[6]*m[13] - m[12]*m[5]*m[10] + m[12]*m[6]*m[9];
    inv[1] = -m[1]*m[10]*m[15] + m[1]*m[11]*m[14] + m[9]*m[2]*m[15] -
             m[9]*m[3]*m[14] - m[13]*m[2]*m[11] + m[13]*m[3]*m[10];
    inv[5] = m[0]*m[10]*m[15] - m[0]*m[11]*m[14] - m[8]*m[2]*m[15] +
             m[8]*m[3]*m[14] + m[12]*m[2]*m[11] - m[12]*m[3]*m[10];
    inv[9] = -m[0]*m[9]*m[15] + m[0]*m[11]*m[13] + m[8]*m[1]*m[15] -
             m[8]*m[3]*m[13] - m[12]*m[1]*m[11] + m[12]*m[3]*m[9];
    inv[13] = m[0]*m[9]*m[14] - m[0]*m[10]*m[13] - m[8]*m[1]*m[14] +
              m[8]*m[2]*m[13] + m[12]*m[1]*m[10] - m[12]*m[2]*m[9];
    inv[2] = m[1]*m[6]*m[15] - m[1]*m[7]*m[14] - m[5]*m[2]*m[15] +
             m[5]*m[3]*m[14] + m[13]*m[2]*m[7] - m[13]*m[3]*m[6];
    inv[6] = -m[0]*m[6]*m[15] + m[0]*m[7]*m[14] + m[4]*m[2]*m[15] -
             m[4]*m[3]*m[14] - m[12]*m[2]*m[7] + m[12]*m[3]*m[6];
    inv[10] = m[0]*m[5]*m[15] - m[0]*m[7]*m[13] - m[4]*m[1]*m[15] +
              m[4]*m[3]*m[13] + m[12]*m[1]*m[7] - m[12]*m[3]*m[5];
    inv[14] = -m[0]*m[5]*m[14] + m[0]*m[6]*m[13] + m[4]*m[1]*m[14] -
              m[4]*m[2]*m[13] - m[12]*m[1]*m[6] + m[12]*m[2]*m[5];
    inv[3] = -m[1]*m[6]*m[11] + m[1]*m[7]*m[10] + m[5]*m[2]*m[11] -
             m[5]*m[3]*m[10] - m[9]*m[2]*m[7] + m[9]*m[3]*m[6];
    inv[7] = m[0]*m[6]*m[11] - m[0]*m[7]*m[10] - m[4]*m[2]*m[11] +
             m[4]*m[3]*m[10] + m[8]*m[2]*m[7] - m[8]*m[3]*m[6];
    inv[11] = -m[0]*m[5]*m[11] + m[0]*m[7]*m[9] + m[4]*m[1]*m[11] -
              m[4]*m[3]*m[9] - m[8]*m[1]*m[7] + m[8]*m[3]*m[5];
    inv[15] = m[0]*m[5]*m[10] - m[0]*m[6]*m[9] - m[4]*m[1]*m[10] +
              m[4]*m[2]*m[9] + m[8]*m[1]*m[6] - m[8]*m[2]*m[5];
    float det = m[0]*inv[0] + m[1]*inv[4] + m[2]*inv[8] + m[3]*inv[12];
    det = 1.0f / det;
    for (int i = 0; i < 16; i++) invOut[i] = inv[i] * det;
}

__global__ void setup_kernel(const float* __restrict__ c2w,
                             const float* __restrict__ K,
                             const float* __restrict__ l2w) {
    float inv[16];
    inv4x4(c2w, inv);
    for (int i = 0; i < 12; i++) g_P.w2c[i] = inv[i];
    inv4x4(l2w, inv);
    for (int i = 0; i < 12; i++) g_P.w2l[i] = inv[i];
    g_P.fx = K[0]; g_P.cx = K[2];
    g_P.fy = K[4]; g_P.cy = K[5];
}

__global__ void zero_kernel(float4* out, int n4) {
    int i = blockIdx.x * blockDim.x + threadIdx.x;
    if (i < n4) out[i] = make_float4(0.f, 0.f, 0.f, 0.f);
}

__device__ __forceinline__ float sigmoid_clip(float x) {
    x = fminf(fmaxf(x, -20.0f), 20.0f);
    return 1.0f / (1.0f + expf(-x));
}

__global__ void splat_kernel(const float* __restrict__ means,
                             const float* __restrict__ sh,
                             const float* __restrict__ opa_c,
                             const float* __restrict__ opa_l,
                             float* __restrict__ out, int n) {
    int g = blockIdx.x * blockDim.x + threadIdx.x;
    if (g >= n) return;

    const float mx = means[3*g + 0];
    const float my = means[3*g + 1];
    const float mz = means[3*g + 2];

    // ---------------- camera ----------------
    {
        const float* M = g_P.w2c;
        // exact-row transform; with identity matrices this is bit-exact = means
        float x = __fadd_rn(__fadd_rn(__fadd_rn(__fmul_rn(M[0],mx), __fmul_rn(M[1],my)), __fmul_rn(M[2],mz)), M[3]);
        float y = __fadd_rn(__fadd_rn(__fadd_rn(__fmul_rn(M[4],mx), __fmul_rn(M[5],my)), __fmul_rn(M[6],mz)), M[7]);
        float z = __fadd_rn(__fadd_rn(__fadd_rn(__fmul_rn(M[8],mx), __fmul_rn(M[9],my)), __fmul_rn(M[10],mz)), M[11]);
        if (z > NEAR_PLANE && z < FAR_PLANE) {
            // u = fx*x/z + cx  (plain mul, div, add -- matches reference fp32)
            float u = __fadd_rn(__fdiv_rn(__fmul_rn(g_P.fx, x), z), g_P.cx);
            float v = __fadd_rn(__fdiv_rn(__fmul_rn(g_P.fy, y), z), g_P.cy);
            float u0 = floorf(u), v0 = floorf(v);
            float fu = __fsub_rn(u, u0), fv = __fsub_rn(v, v0);
            int u0i = (int)u0, v0i = (int)v0;
            if (u0i >= -1 && u0i < W_IMG && v0i >= -1 && v0i < H_IMG) {
                float oc = sigmoid_clip(opa_c[g]);
                float cr = sigmoid_clip(sh[48*g + 0]);
                float cg = sigmoid_clip(sh[48*g + 1]);
                float cb = sigmoid_clip(sh[48*g + 2]);
                float ofu = __fsub_rn(1.0f, fu), ofv = __fsub_rn(1.0f, fv);
                float cw[4] = { __fmul_rn(ofu, ofv), __fmul_rn(fu, ofv),
                                __fmul_rn(ofu, fv),  __fmul_rn(fu, fv) };
                #pragma unroll
                for (int c = 0; c < 4; c++) {
                    int ui = u0i + (c & 1);
                    int vi = v0i + (c >> 1);
                    if (ui >= 0 && ui < W_IMG && vi >= 0 && vi < H_IMG) {
                        float ww = __fmul_rn(oc, cw[c]);
                        int pix = vi * W_IMG + ui;
                        atomicAdd(&out[OFF_RGB + 3*pix + 0], __fmul_rn(cr, ww));
                        atomicAdd(&out[OFF_RGB + 3*pix + 1], __fmul_rn(cg, ww));
                        atomicAdd(&out[OFF_RGB + 3*pix + 2], __fmul_rn(cb, ww));
                        atomicAdd(&out[OFF_DEPTH + pix], __fmul_rn(z, ww));
                        atomicAdd(&out[OFF_ALPHA + pix], ww);
                    }
                }
            }
        }
    }

    // ---------------- lidar ----------------
    {
        const float* M = g_P.w2l;
        float x = __fadd_rn(__fadd_rn(__fadd_rn(__fmul_rn(M[0],mx), __fmul_rn(M[1],my)), __fmul_rn(M[2],mz)), M[3]);
        float y = __fadd_rn(__fadd_rn(__fadd_rn(__fmul_rn(M[4],mx), __fmul_rn(M[5],my)), __fmul_rn(M[6],mz)), M[7]);
        float z = __fadd_rn(__fadd_rn(__fadd_rn(__fmul_rn(M[8],mx), __fmul_rn(M[9],my)), __fmul_rn(M[10],mz)), M[11]);
        float r = sqrtf(__fadd_rn(__fadd_rn(__fmul_rn(x,x), __fmul_rn(y,y)), __fmul_rn(z,z)));
        float el = asinf(__fdiv_rn(z, fmaxf(r, 1e-6f)));
        if (r > NEAR_PLANE && r < FAR_PLANE &&
            el >= FMIN_F && el <= FMAX_F) {
            float az = atan2f(y, x);
            // uL = (az / 2pi + 0.5) * WL   (division, matching reference)
            float uL = __fmul_rn(__fadd_rn(__fdiv_rn(az, TWO_PI_F), 0.5f), (float)WL_IMG);
            // vL = (fmax - el) / (fmax - fmin) * (HL-1)
            float vL = __fmul_rn(__fdiv_rn(__fsub_rn(FMAX_F, el), FRANGE_F), (float)(HL_IMG - 1));
            float u0 = floorf(uL), v0 = floorf(vL);
            float fu = __fsub_rn(uL, u0), fv = __fsub_rn(vL, v0);
            int u0i = (int)u0, v0i = (int)v0;
            float ol = sigmoid_clip(opa_l[g]);
            float ofu = __fsub_rn(1.0f, fu), ofv = __fsub_rn(1.0f, fv);
            float cw[4] = { __fmul_rn(ofu, ofv), __fmul_rn(fu, ofv),
                            __fmul_rn(ofu, fv),  __fmul_rn(fu, fv) };
            #pragma unroll
            for (int c = 0; c < 4; c++) {
                int ui = (u0i + (c & 1)) & (WL_IMG - 1);  // wrap (power of 2)
                int vi = v0i + (c >> 1);
                if (vi >= 0 && vi < HL_IMG) {
                    float ww = __fmul_rn(ol, cw[c]);
                    int pix = vi * WL_IMG + ui;
                    atomicAdd(&out[OFF_LD + pix], __fmul_rn(r, ww));
                    atomicAdd(&out[OFF_LA + pix], ww);
                }
            }
        }
    }
}

__global__ void finalize_kernel(float* __restrict__ out) {
    int i = blockIdx.x * blockDim.x + threadIdx.x;
    if (i < CAM_PIX) {
        float w = out[OFF_ALPHA + i];
        float wpe = __fadd_rn(w, EPS);
        float a = fminf(fmaxf(w, 0.0f), 1.0f);
        out[OFF_RGB + 3*i + 0] = __fmul_rn(__fdiv_rn(out[OFF_RGB + 3*i + 0], wpe), a);
        out[OFF_RGB + 3*i + 1] = __fmul_rn(__fdiv_rn(out[OFF_RGB + 3*i + 1], wpe), a);
        out[OFF_RGB + 3*i + 2] = __fmul_rn(__fdiv_rn(out[OFF_RGB + 3*i + 2], wpe), a);
        out[OFF_DEPTH + i] = __fdiv_rn(out[OFF_DEPTH + i], wpe);
        out[OFF_ALPHA + i] = a;
    } else if (i < CAM_PIX + LID_PIX) {
        int j = i - CAM_PIX;
        float w = out[OFF_LA + j];
        out[OFF_LD + j] = __fdiv_rn(out[OFF_LD + j], __fadd_rn(w, EPS));
        out[OFF_LA + j] = fminf(fmaxf(w, 0.0f), 1.0f);
    }
}

extern "C" void kernel_launch(void* const* d_in, const int* in_sizes, int n_in,
                              void* d_out, int out_size) {
    const float* means = (const float*)d_in[0];
    const float* sh    = (const float*)d_in[3];
    const float* opa_c = (const float*)d_in[4];
    const float* opa_l = (const float*)d_in[5];
    const float* c2w   = (const float*)d_in[6];
    const float* K     = (const float*)d_in[7];
    const float* l2w   = (const float*)d_in[8];
    float* out = (float*)d_out;

    int n = in_sizes[0] / 3;

    int n4 = out_size / 4;
    zero_kernel<<<(n4 + 255) / 256, 256>>>((float4*)out, n4);
    setup_kernel<<<1, 1>>>(c2w, K, l2w);
    splat_kernel<<<(n + 255) / 256, 256>>>(means, sh, opa_c, opa_l, out, n);
    int tot = CAM_PIX + LID_PIX;
    finalize_kernel<<<(tot + 255) / 256, 256>>>(out);
}

// round 3
// speedup vs baseline: 1.1929x; 1.1929x over previous
#include <cuda_runtime.h>
#include <math.h>

// ---------------------------------------------------------------------------
// GaussianSceneModel: 1M gaussians -> camera (rgb, depth, alpha) + lidar
// (depth, alpha) via bilinear scatter splatting.
// Projection arithmetic uses explicit IEEE intrinsics to bit-match fp32 ref.
// R3: vectorized finalize (4 px/thread, float4), asinf pre-filter in splat.
// ---------------------------------------------------------------------------

#define W_IMG   1600
#define H_IMG   900
#define WL_IMG  1024
#define HL_IMG  128
#define CAM_PIX (W_IMG * H_IMG)          // 1,440,000
#define LID_PIX (WL_IMG * HL_IMG)        // 131,072
#define OFF_RGB   0
#define OFF_DEPTH (3 * CAM_PIX)
#define OFF_ALPHA (4 * CAM_PIX)
#define OFF_LD    (5 * CAM_PIX)
#define OFF_LA    (5 * CAM_PIX + LID_PIX)

#define FMIN_F ((float)(-0.4363323129985824))
#define FMAX_F ((float)(0.05235987755982988))
#define FRANGE_F ((float)(0.05235987755982988 + 0.4363323129985824))
#define TWO_PI_F ((float)(6.283185307179586))
// sin bounds for the elevation pre-filter, widened by a safety margin.
#define SIN_FMIN_LO (-0.42261826f - 1e-4f)
#define SIN_FMAX_HI ( 0.05233596f + 1e-4f)
#define NEAR_PLANE 1.0f
#define FAR_PLANE  100.0f
#define EPS 1e-8f

struct Params {
    float w2c[12];
    float w2l[12];
    float fx, fy, cx, cy;
};
__device__ Params g_P;

__device__ void inv4x4(const float* m, float* invOut) {
    float inv[16];
    inv[0] = m[5]*m[10]*m[15] - m[5]*m[11]*m[14] - m[9]*m[6]*m[15] +
             m[9]*m[7]*m[14] + m[13]*m[6]*m[11] - m[13]*m[7]*m[10];
    inv[4] = -m[4]*m[10]*m[15] + m[4]*m[11]*m[14] + m[8]*m[6]*m[15] -
             m[8]*m[7]*m[14] - m[12]*m[6]*m[11] + m[12]*m[7]*m[10];
    inv[8] = m[4]*m[9]*m[15] - m[4]*m[11]*m[13] - m[8]*m[5]*m[15] +
             m[8]*m[7]*m[13] + m[12]*m[5]*m[11] - m[12]*m[7]*m[9];
    inv[12] = -m[4]*m[9]*m[14] + m[4]*m[10]*m[13] + m[8]*m[5]*m[14] -
              m[8]*m[6]*m[13] - m[12]*m[5]*m[10] + m[12]*m[6]*m[9];
    inv[1] = -m[1]*m[10]*m[15] + m[1]*m[11]*m[14] + m[9]*m[2]*m[15] -
             m[9]*m[3]*m[14] - m[13]*m[2]*m[11] + m[13]*m[3]*m[10];
    inv[5] = m[0]*m[10]*m[15] - m[0]*m[11]*m[14] - m[8]*m[2]*m[15] +
             m[8]*m[3]*m[14] + m[12]*m[2]*m[11] - m[12]*m[3]*m[10];
    inv[9] = -m[0]*m[9]*m[15] + m[0]*m[11]*m[13] + m[8]*m[1]*m[15] -
             m[8]*m[3]*m[13] - m[12]*m[1]*m[11] + m[12]*m[3]*m[9];
    inv[13] = m[0]*m[9]*m[14] - m[0]*m[10]*m[13] - m[8]*m[1]*m[14] +
              m[8]*m[2]*m[13] + m[12]*m[1]*m[10] - m[12]*m[2]*m[9];
    inv[2] = m[1]*m[6]*m[15] - m[1]*m[7]*m[14] - m[5]*m[2]*m[15] +
             m[5]*m[3]*m[14] + m[13]*m[2]*m[7] - m[13]*m[3]*m[6];
    inv[6] = -m[0]*m[6]*m[15] + m[0]*m[7]*m[14] + m[4]*m[2]*m[15] -
             m[4]*m[3]*m[14] - m[12]*m[2]*m[7] + m[12]*m[3]*m[6];
    inv[10] = m[0]*m[5]*m[15] - m[0]*m[7]*m[13] - m[4]*m[1]*m[15] +
              m[4]*m[3]*m[13] + m[12]*m[1]*m[7] - m[12]*m[3]*m[5];
    inv[14] = -m[0]*m[5]*m[14] + m[0]*m[6]*m[13] + m[4]*m[1]*m[14] -
              m[4]*m[2]*m[13] - m[12]*m[1]*m[6] + m[12]*m[2]*m[5];
    inv[3] = -m[1]*m[6]*m[11] + m[1]*m[7]*m[10] + m[5]*m[2]*m[11] -
             m[5]*m[3]*m[10] - m[9]*m[2]*m[7] + m[9]*m[3]*m[6];
    inv[7] = m[0]*m[6]*m[11] - m[0]*m[7]*m[10] - m[4]*m[2]*m[11] +
             m[4]*m[3]*m[10] + m[8]*m[2]*m[7] - m[8]*m[3]*m[6];
    inv[11] = -m[0]*m[5]*m[11] + m[0]*m[7]*m[9] + m[4]*m[1]*m[11] -
              m[4]*m[3]*m[9] - m[8]*m[1]*m[7] + m[8]*m[3]*m[5];
    inv[15] = m[0]*m[5]*m[10] - m[0]*m[6]*m[9] - m[4]*m[1]*m[10] +
              m[4]*m[2]*m[9] + m[8]*m[1]*m[6] - m[8]*m[2]*m[5];
    float det = m[0]*inv[0] + m[1]*inv[4] + m[2]*inv[8] + m[3]*inv[12];
    det = 1.0f / det;
    for (int i = 0; i < 16; i++) invOut[i] = inv[i] * det;
}

__global__ void setup_kernel(const float* __restrict__ c2w,
                             const float* __restrict__ K,
                             const float* __restrict__ l2w) {
    float inv[16];
    inv4x4(c2w, inv);
    for (int i = 0; i < 12; i++) g_P.w2c[i] = inv[i];
    inv4x4(l2w, inv);
    for (int i = 0; i < 12; i++) g_P.w2l[i] = inv[i];
    g_P.fx = K[0]; g_P.cx = K[2];
    g_P.fy = K[4]; g_P.cy = K[5];
}

__global__ void zero_kernel(float4* out, int n4) {
    int i = blockIdx.x * blockDim.x + threadIdx.x;
    if (i < n4) out[i] = make_float4(0.f, 0.f, 0.f, 0.f);
}

__device__ __forceinline__ float sigmoid_clip(float x) {
    x = fminf(fmaxf(x, -20.0f), 20.0f);
    return 1.0f / (1.0f + expf(-x));
}

__global__ void splat_kernel(const float* __restrict__ means,
                             const float* __restrict__ sh,
                             const float* __restrict__ opa_c,
                             const float* __restrict__ opa_l,
                             float* __restrict__ out, int n) {
    int g = blockIdx.x * blockDim.x + threadIdx.x;
    if (g >= n) return;

    const float mx = means[3*g + 0];
    const float my = means[3*g + 1];
    const float mz = means[3*g + 2];

    // ---------------- camera ----------------
    {
        const float* M = g_P.w2c;
        float x = __fadd_rn(__fadd_rn(__fadd_rn(__fmul_rn(M[0],mx), __fmul_rn(M[1],my)), __fmul_rn(M[2],mz)), M[3]);
        float y = __fadd_rn(__fadd_rn(__fadd_rn(__fmul_rn(M[4],mx), __fmul_rn(M[5],my)), __fmul_rn(M[6],mz)), M[7]);
        float z = __fadd_rn(__fadd_rn(__fadd_rn(__fmul_rn(M[8],mx), __fmul_rn(M[9],my)), __fmul_rn(M[10],mz)), M[11]);
        if (z > NEAR_PLANE && z < FAR_PLANE) {
            float u = __fadd_rn(__fdiv_rn(__fmul_rn(g_P.fx, x), z), g_P.cx);
            float v = __fadd_rn(__fdiv_rn(__fmul_rn(g_P.fy, y), z), g_P.cy);
            float u0 = floorf(u), v0 = floorf(v);
            float fu = __fsub_rn(u, u0), fv = __fsub_rn(v, v0);
            int u0i = (int)u0, v0i = (int)v0;
            if (u0i >= -1 && u0i < W_IMG && v0i >= -1 && v0i < H_IMG) {
                float oc = sigmoid_clip(opa_c[g]);
                float cr = sigmoid_clip(sh[48*g + 0]);
                float cg = sigmoid_clip(sh[48*g + 1]);
                float cb = sigmoid_clip(sh[48*g + 2]);
                float ofu = __fsub_rn(1.0f, fu), ofv = __fsub_rn(1.0f, fv);
                float cw[4] = { __fmul_rn(ofu, ofv), __fmul_rn(fu, ofv),
                                __fmul_rn(ofu, fv),  __fmul_rn(fu, fv) };
                #pragma unroll
                for (int c = 0; c < 4; c++) {
                    int ui = u0i + (c & 1);
                    int vi = v0i + (c >> 1);
                    if (ui >= 0 && ui < W_IMG && vi >= 0 && vi < H_IMG) {
                        float ww = __fmul_rn(oc, cw[c]);
                        int pix = vi * W_IMG + ui;
                        atomicAdd(&out[OFF_RGB + 3*pix + 0], __fmul_rn(cr, ww));
                        atomicAdd(&out[OFF_RGB + 3*pix + 1], __fmul_rn(cg, ww));
                        atomicAdd(&out[OFF_RGB + 3*pix + 2], __fmul_rn(cb, ww));
                        atomicAdd(&out[OFF_DEPTH + pix], __fmul_rn(z, ww));
                        atomicAdd(&out[OFF_ALPHA + pix], ww);
                    }
                }
            }
        }
    }

    // ---------------- lidar ----------------
    {
        const float* M = g_P.w2l;
        float x = __fadd_rn(__fadd_rn(__fadd_rn(__fmul_rn(M[0],mx), __fmul_rn(M[1],my)), __fmul_rn(M[2],mz)), M[3]);
        float y = __fadd_rn(__fadd_rn(__fadd_rn(__fmul_rn(M[4],mx), __fmul_rn(M[5],my)), __fmul_rn(M[6],mz)), M[7]);
        float z = __fadd_rn(__fadd_rn(__fadd_rn(__fmul_rn(M[8],mx), __fmul_rn(M[9],my)), __fmul_rn(M[10],mz)), M[11]);
        float r = sqrtf(__fadd_rn(__fadd_rn(__fmul_rn(x,x), __fmul_rn(y,y)), __fmul_rn(z,z)));
        if (r > NEAR_PLANE && r < FAR_PLANE) {
            float s = __fdiv_rn(z, fmaxf(r, 1e-6f));
            // cheap widened pre-filter: skip asinf for clearly-out gaussians
            if (s >= SIN_FMIN_LO && s <= SIN_FMAX_HI) {
                float el = asinf(s);
                if (el >= FMIN_F && el <= FMAX_F) {
                    float az = atan2f(y, x);
                    float uL = __fmul_rn(__fadd_rn(__fdiv_rn(az, TWO_PI_F), 0.5f), (float)WL_IMG);
                    float vL = __fmul_rn(__fdiv_rn(__fsub_rn(FMAX_F, el), FRANGE_F), (float)(HL_IMG - 1));
                    float u0 = floorf(uL), v0 = floorf(vL);
                    float fu = __fsub_rn(uL, u0), fv = __fsub_rn(vL, v0);
                    int u0i = (int)u0, v0i = (int)v0;
                    float ol = sigmoid_clip(opa_l[g]);
                    float ofu = __fsub_rn(1.0f, fu), ofv = __fsub_rn(1.0f, fv);
                    float cw[4] = { __fmul_rn(ofu, ofv), __fmul_rn(fu, ofv),
                                    __fmul_rn(ofu, fv),  __fmul_rn(fu, fv) };
                    #pragma unroll
                    for (int c = 0; c < 4; c++) {
                        int ui = (u0i + (c & 1)) & (WL_IMG - 1);
                        int vi = v0i + (c >> 1);
                        if (vi >= 0 && vi < HL_IMG) {
                            float ww = __fmul_rn(ol, cw[c]);
                            int pix = vi * WL_IMG + ui;
                            atomicAdd(&out[OFF_LD + pix], __fmul_rn(r, ww));
                            atomicAdd(&out[OFF_LA + pix], ww);
                        }
                    }
                }
            }
        }
    }
}

// 4 pixels per thread, fully vectorized float4 traffic.
#define CAM_T (CAM_PIX / 4)   // 360,000
#define LID_T (LID_PIX / 4)   // 32,768
__global__ void finalize_kernel(float* __restrict__ out) {
    int t = blockIdx.x * blockDim.x + threadIdx.x;
    if (t < CAM_T) {
        float4* rgb4 = (float4*)(out + OFF_RGB);     // 3 float4 per thread
        float4* dep4 = (float4*)(out + OFF_DEPTH);
        float4* alp4 = (float4*)(out + OFF_ALPHA);
        float4 w4 = alp4[t];
        float4 d4 = dep4[t];
        float4 r0 = rgb4[3*t + 0];
        float4 r1 = rgb4[3*t + 1];
        float4 r2 = rgb4[3*t + 2];
        float w[4]   = { w4.x, w4.y, w4.z, w4.w };
        float d[4]   = { d4.x, d4.y, d4.z, d4.w };
        float rgb[12] = { r0.x, r0.y, r0.z, r0.w, r1.x, r1.y, r1.z, r1.w,
                          r2.x, r2.y, r2.z, r2.w };
        float a[4], s[4];
        #pragma unroll
        for (int i = 0; i < 4; i++) {
            float wpe = __fadd_rn(w[i], EPS);
            a[i] = fminf(fmaxf(w[i], 0.0f), 1.0f);
            float inv = __fdiv_rn(1.0f, wpe);        // one div, reused
            d[i] = __fmul_rn(d[i], inv);
            s[i] = inv;                              // rgb: (x/wpe)*a
        }
        #pragma unroll
        for (int i = 0; i < 4; i++) {
            #pragma unroll
            for (int c = 0; c < 3; c++)
                rgb[3*i + c] = __fmul_rn(__fmul_rn(rgb[3*i + c], s[i]), a[i]);
        }
        rgb4[3*t + 0] = make_float4(rgb[0], rgb[1], rgb[2],  rgb[3]);
        rgb4[3*t + 1] = make_float4(rgb[4], rgb[5], rgb[6],  rgb[7]);
        rgb4[3*t + 2] = make_float4(rgb[8], rgb[9], rgb[10], rgb[11]);
        dep4[t] = make_float4(d[0], d[1], d[2], d[3]);
        alp4[t] = make_float4(a[0], a[1], a[2], a[3]);
    } else if (t < CAM_T + LID_T) {
        int j = t - CAM_T;
        float4* ld4 = (float4*)(out + OFF_LD);
        float4* la4 = (float4*)(out + OFF_LA);
        float4 w4 = la4[j];
        float4 d4 = ld4[j];
        float w[4] = { w4.x, w4.y, w4.z, w4.w };
        float d[4] = { d4.x, d4.y, d4.z, d4.w };
        #pragma unroll
        for (int i = 0; i < 4; i++) {
            d[i] = __fdiv_rn(d[i], __fadd_rn(w[i], EPS));
            w[i] = fminf(fmaxf(w[i], 0.0f), 1.0f);
        }
        ld4[j] = make_float4(d[0], d[1], d[2], d[3]);
        la4[j] = make_float4(w[0], w[1], w[2], w[3]);
    }
}

extern "C" void kernel_launch(void* const* d_in, const int* in_sizes, int n_in,
                              void* d_out, int out_size) {
    const float* means = (const float*)d_in[0];
    const float* sh    = (const float*)d_in[3];
    const float* opa_c = (const float*)d_in[4];
    const float* opa_l = (const float*)d_in[5];
    const float* c2w   = (const float*)d_in[6];
    const float* K     = (const float*)d_in[7];
    const float* l2w   = (const float*)d_in[8];
    float* out = (float*)d_out;

    int n = in_sizes[0] / 3;

    int n4 = out_size / 4;
    zero_kernel<<<(n4 + 255) / 256, 256>>>((float4*)out, n4);
    setup_kernel<<<1, 1>>>(c2w, K, l2w);
    splat_kernel<<<(n + 255) / 256, 256>>>(means, sh, opa_c, opa_l, out, n);
    int tot = CAM_T + LID_T;
    finalize_kernel<<<(tot + 255) / 256, 256>>>(out);
}